// round 1
// baseline (speedup 1.0000x reference)
#include <cuda_runtime.h>

#define T_STEPS 2048
#define N_IN    512
#define N_OUT   512
#define N_OBS   256

// One warp owns one output row. W row lives entirely in registers (16 floats/lane,
// as 4 float4 chunks mapped to columns g*128 + lane*4 .. +3 for coalesced loads).
// Per step: partial dot -> warp butterfly reduce -> sigmoid -> write observed ->
// fused (W update + next-step partial dot) -> prefetch x(t+2).
__global__ __launch_bounds__(128, 1)
void circuit_scan_kernel(const float* __restrict__ X,
                         const float* __restrict__ W_init,
                         const float* __restrict__ theta,
                         const int*   __restrict__ obs,
                         float*       __restrict__ out)
{
    const int warp = (blockIdx.x * blockDim.x + threadIdx.x) >> 5;
    const int lane = threadIdx.x & 31;
    if (warp >= N_OUT) return;
    const int row = warp;

    const float lr  = 1.0f / (float)N_IN;
    const float th0 = __ldg(&theta[0]) * lr;   // lr * theta0
    const float th1 = __ldg(&theta[1]) * lr;   // lr * theta1

    // Load W row into registers (coalesced float4 per 128-col group).
    float4 W[4];
#pragma unroll
    for (int g = 0; g < 4; g++)
        W[g] = *reinterpret_cast<const float4*>(&W_init[row * N_IN + g * 128 + lane * 4]);

    // Find [start, start+count) range of this row in the SORTED observed_idx
    // (handles duplicates naturally). All lanes compute identically.
    int start = 0, count = 0;
#pragma unroll 8
    for (int i = 0; i < N_OBS; i++) {
        int v = __ldg(&obs[i]);
        start += (v < row) ? 1 : 0;
        count += (v == row) ? 1 : 0;
    }

    // Software pipeline: xr = x_t, xn = x_{t+1}
    float4 xr[4], xn[4];
#pragma unroll
    for (int g = 0; g < 4; g++)
        xr[g] = *reinterpret_cast<const float4*>(&X[0 * N_IN + g * 128 + lane * 4]);
#pragma unroll
    for (int g = 0; g < 4; g++)
        xn[g] = *reinterpret_cast<const float4*>(&X[1 * N_IN + g * 128 + lane * 4]);

    // Initial partial dot for t = 0 (4 independent accumulator chains).
    float acc;
    {
        float a0 = 0.f, a1 = 0.f, a2 = 0.f, a3 = 0.f;
#pragma unroll
        for (int g = 0; g < 4; g++) {
            a0 = fmaf(W[g].x, xr[g].x, a0);
            a1 = fmaf(W[g].y, xr[g].y, a1);
            a2 = fmaf(W[g].z, xr[g].z, a2);
            a3 = fmaf(W[g].w, xr[g].w, a3);
        }
        acc = (a0 + a1) + (a2 + a3);
    }

    for (int t = 0; t < T_STEPS; t++) {
        // Butterfly reduce: all lanes end with the full dot product.
        float s = acc;
#pragma unroll
        for (int o = 16; o > 0; o >>= 1)
            s += __shfl_xor_sync(0xffffffffu, s, o);

        const float y = 1.0f / (1.0f + __expf(-s));

        // Write observed outputs (count is tiny; usually 0 or 1 per row).
        for (int k = lane; k < count; k += 32)
            out[t * N_OBS + start + k] = y;

        // W_{t+1}[j] = (1 + lr*th1*y^2) * W_t[j] + (lr*th0*y) * x_t[j]
        const float a = fmaf(th1 * y, y, 1.0f);
        const float b = th0 * y;

        // Fused update + partial dot for step t+1 (uses xn = x_{t+1}).
        float a0 = 0.f, a1 = 0.f, a2 = 0.f, a3 = 0.f;
#pragma unroll
        for (int g = 0; g < 4; g++) {
            W[g].x = fmaf(a, W[g].x, b * xr[g].x);
            W[g].y = fmaf(a, W[g].y, b * xr[g].y);
            W[g].z = fmaf(a, W[g].z, b * xr[g].z);
            W[g].w = fmaf(a, W[g].w, b * xr[g].w);
            a0 = fmaf(W[g].x, xn[g].x, a0);
            a1 = fmaf(W[g].y, xn[g].y, a1);
            a2 = fmaf(W[g].z, xn[g].z, a2);
            a3 = fmaf(W[g].w, xn[g].w, a3);
        }
        acc = (a0 + a1) + (a2 + a3);

        // Shift pipeline and prefetch x_{t+2} (clamped; last values unused).
#pragma unroll
        for (int g = 0; g < 4; g++) xr[g] = xn[g];
        const int tn = (t + 2 < T_STEPS) ? (t + 2) : (T_STEPS - 1);
#pragma unroll
        for (int g = 0; g < 4; g++)
            xn[g] = *reinterpret_cast<const float4*>(&X[tn * N_IN + g * 128 + lane * 4]);
    }
}

extern "C" void kernel_launch(void* const* d_in, const int* in_sizes, int n_in,
                              void* d_out, int out_size)
{
    const float* X      = (const float*)d_in[0];   // [2048, 512]
    const float* W_init = (const float*)d_in[1];   // [512, 512]
    const float* theta  = (const float*)d_in[2];   // [2]
    const int*   obs    = (const int*)d_in[3];     // [256], sorted
    float*       out    = (float*)d_out;           // [2048, 256]

    (void)in_sizes; (void)n_in; (void)out_size;

    // 512 rows -> 512 warps -> 128 CTAs of 128 threads (1 CTA/SM, 1 warp/SMSP).
    circuit_scan_kernel<<<128, 128>>>(X, W_init, theta, obs, out);
}

// round 3
// speedup vs baseline: 1.3488x; 1.3488x over previous
#include <cuda_runtime.h>

#define T_STEPS 2048
#define N_IN    512
#define N_OUT   512
#define N_OBS   256

// Scratch (padded to keep prefetch reads in-bounds):
//   g_c[t] = x_t . x_{t+1}   (0 for t >= T-1)
//   g_d[t] = x_t . x_{t+2}   (0 for t >= T-2)
__device__ __align__(16) float g_c[T_STEPS + 16];
__device__ __align__(16) float g_d[T_STEPS + 16];

__device__ __forceinline__ float warp_bfly(float v) {
#pragma unroll
    for (int o = 16; o > 0; o >>= 1)
        v += __shfl_xor_sync(0xffffffffu, v, o);
    return v;
}

// ---------------- pre-kernel: c[t], d[t] in parallel (one warp per t) ----
__global__ void precompute_cd_kernel(const float* __restrict__ X) {
    const int t    = blockIdx.x * (blockDim.x >> 5) + (threadIdx.x >> 5);
    const int lane = threadIdx.x & 31;
    if (t >= T_STEPS + 8) return;

    const int t0 = (t     < T_STEPS) ? t     : T_STEPS - 1;
    const int t1 = (t + 1 < T_STEPS) ? t + 1 : T_STEPS - 1;
    const int t2 = (t + 2 < T_STEPS) ? t + 2 : T_STEPS - 1;

    float pc = 0.0f, pd = 0.0f;
#pragma unroll
    for (int g = 0; g < 4; g++) {
        const float4 a  = *reinterpret_cast<const float4*>(&X[t0 * N_IN + g * 128 + lane * 4]);
        const float4 b1 = *reinterpret_cast<const float4*>(&X[t1 * N_IN + g * 128 + lane * 4]);
        const float4 b2 = *reinterpret_cast<const float4*>(&X[t2 * N_IN + g * 128 + lane * 4]);
        pc = fmaf(a.x, b1.x, pc); pc = fmaf(a.y, b1.y, pc);
        pc = fmaf(a.z, b1.z, pc); pc = fmaf(a.w, b1.w, pc);
        pd = fmaf(a.x, b2.x, pd); pd = fmaf(a.y, b2.y, pd);
        pd = fmaf(a.z, b2.z, pd); pd = fmaf(a.w, b2.w, pd);
    }
    const float c = warp_bfly(pc);
    const float d = warp_bfly(pd);
    if (lane == 0) {
        g_c[t] = (t < T_STEPS - 1) ? c : 0.0f;
        g_d[t] = (t < T_STEPS - 2) ? d : 0.0f;
    }
}

// ---------------- main scan: one warp per output row ----------------
// W = alpha * V. Reduction result deferred TWO iterations:
//   at iter t:  u = alpha_{t-1} * q_{t-2};  v = a_{t-1}*u + b_{t-1}*d_{t-1}
//               s_{t+1} = a_t * v + b_t * c_t
//   q_t = bfly( V_{t+1} . x_{t+3} )  -- consumed at iter t+2
__global__ __launch_bounds__(128, 1)
void circuit_scan_kernel(const float* __restrict__ X,
                         const float* __restrict__ W_init,
                         const float* __restrict__ theta,
                         const int*   __restrict__ obs,
                         float*       __restrict__ out)
{
    const int warp = blockIdx.x * 4 + (threadIdx.x >> 5);
    const int lane = threadIdx.x & 31;
    const int row  = warp;

    const float lr  = 1.0f / (float)N_IN;
    const float th0 = __ldg(&theta[0]) * lr;
    const float th1 = __ldg(&theta[1]) * lr;

    // [start, start+count) = this row's slots in the sorted observed_idx
    int start = 0, count = 0;
#pragma unroll 8
    for (int i = 0; i < N_OBS; i++) {
        const int v = __ldg(&obs[i]);
        start += (v <  row) ? 1 : 0;
        count += (v == row) ? 1 : 0;
    }

    // V = W row (alpha = 1); coalesced float4 per 128-col group
    float4 V[4];
#pragma unroll
    for (int g = 0; g < 4; g++)
        V[g] = *reinterpret_cast<const float4*>(&W_init[row * N_IN + g * 128 + lane * 4]);

    // x ring: xb[k&3] = x_k, k = 0..3
    float4 xb[4][4];
#pragma unroll
    for (int k = 0; k < 4; k++)
#pragma unroll
        for (int g = 0; g < 4; g++)
            xb[k][g] = *reinterpret_cast<const float4*>(&X[k * N_IN + g * 128 + lane * 4]);

    // Prologue reduces: s0 = V0.x0, q2 = V0.x1, q1 = V0.x2
    float p0 = 0.f, p1 = 0.f, p2 = 0.f;
#pragma unroll
    for (int g = 0; g < 4; g++) {
        p0 = fmaf(V[g].x, xb[0][g].x, p0); p0 = fmaf(V[g].y, xb[0][g].y, p0);
        p0 = fmaf(V[g].z, xb[0][g].z, p0); p0 = fmaf(V[g].w, xb[0][g].w, p0);
        p1 = fmaf(V[g].x, xb[1][g].x, p1); p1 = fmaf(V[g].y, xb[1][g].y, p1);
        p1 = fmaf(V[g].z, xb[1][g].z, p1); p1 = fmaf(V[g].w, xb[1][g].w, p1);
        p2 = fmaf(V[g].x, xb[2][g].x, p2); p2 = fmaf(V[g].y, xb[2][g].y, p2);
        p2 = fmaf(V[g].z, xb[2][g].z, p2); p2 = fmaf(V[g].w, xb[2][g].w, p2);
    }
    float s  = warp_bfly(p0);   // s_0
    float q2 = warp_bfly(p1);   // plays q_{-2} = V_0.x_1  (with a_{-1}=1, b_{-1}=0)
    float q1 = warp_bfly(p2);   // plays q_{-1} = V_0.x_2

    float alpha = 1.0f;                       // alpha_t
    float al_pr = 1.0f, a_pr = 1.0f, b_pr = 0.0f;  // alpha_{t-1}, a_{t-1}, b_{t-1}
    float c_cur = __ldg(&g_c[0]);             // c_t
    float d_pr  = 0.0f;                       // d_{t-1}

    for (int tb = 0; tb < T_STEPS; tb += 4) {
#pragma unroll
        for (int j = 0; j < 4; j++) {
            const int t = tb + j;

            // prefetch next-iteration c/d (L1-hot after first touch)
            const float c_nxt = __ldg(&g_c[t + 1]);
            const float d_cur = __ldg(&g_d[t]);

            // v-chain: uses only iteration-start-ready values (parallel w/ sigmoid)
            const float u = al_pr * q2;
            const float v = fmaf(a_pr, u, b_pr * d_pr);

            // sigmoid
            const float e = __expf(-s);
            const float y = __fdividef(1.0f, 1.0f + e);

            // observed outputs
            for (int k = lane; k < count; k += 32)
                out[t * N_OBS + start + k] = y;

            const float b = th0 * y;
            const float a = fmaf(th1 * y, y, 1.0f);
            s = fmaf(a, v, b * c_cur);               // s_{t+1}

            const float alpha_nx = alpha * a;        // alpha_{t+1}
            const float beta     = __fdividef(b, alpha_nx);

            // shift scalar pipeline
            al_pr = alpha; a_pr = a; b_pr = b;
            alpha = alpha_nx;
            c_cur = c_nxt; d_pr = d_cur;

            // V update (x_t) fused with partial dot against x_{t+3}
            float4* xt = xb[j];
            float4* xd = xb[(j + 3) & 3];
            float w0 = 0.f, w1 = 0.f, w2 = 0.f, w3 = 0.f;
#pragma unroll
            for (int g = 0; g < 4; g++) {
                V[g].x = fmaf(beta, xt[g].x, V[g].x);
                V[g].y = fmaf(beta, xt[g].y, V[g].y);
                V[g].z = fmaf(beta, xt[g].z, V[g].z);
                V[g].w = fmaf(beta, xt[g].w, V[g].w);
                w0 = fmaf(V[g].x, xd[g].x, w0);
                w1 = fmaf(V[g].y, xd[g].y, w1);
                w2 = fmaf(V[g].z, xd[g].z, w2);
                w3 = fmaf(V[g].w, xd[g].w, w3);
            }
            const float q_new = warp_bfly((w0 + w1) + (w2 + w3)); // V_{t+1}.x_{t+3}
            q2 = q1;
            q1 = q_new;

            // refill ring slot with x_{t+4} (clamped; tail values unused)
            int tn = t + 4;
            if (tn > T_STEPS - 1) tn = T_STEPS - 1;
#pragma unroll
            for (int g = 0; g < 4; g++)
                xb[j][g] = *reinterpret_cast<const float4*>(&X[tn * N_IN + g * 128 + lane * 4]);
        }
    }
}

extern "C" void kernel_launch(void* const* d_in, const int* in_sizes, int n_in,
                              void* d_out, int out_size)
{
    const float* X      = (const float*)d_in[0];   // [2048, 512]
    const float* W_init = (const float*)d_in[1];   // [512, 512]
    const float* theta  = (const float*)d_in[2];   // [2]
    const int*   obs    = (const int*)d_in[3];     // [256], sorted
    float*       out    = (float*)d_out;           // [2048, 256]

    (void)in_sizes; (void)n_in; (void)out_size;

    // 2056 warps for c/d: 257 CTAs x 256 threads (8 warps each)
    precompute_cd_kernel<<<257, 256>>>(X);
    // 512 rows -> 512 warps -> 128 CTAs x 128 threads (1 CTA/SM, 1 warp/SMSP)
    circuit_scan_kernel<<<128, 128>>>(X, W_init, theta, obs, out);
}